// round 1
// baseline (speedup 1.0000x reference)
#include <cuda_runtime.h>
#include <math.h>

#define DD   2048
#define HH   8
#define KVH  2
#define HDIM 256
#define SS   4096
#define FFD  8192
#define PLD  256
#define LL   8
#define POSI 2048
#define EPSF 1e-6f

// ---------------- scratch (device globals; no allocation allowed) ----------------
__device__ float g_h[DD];
__device__ float g_hn[DD];
__device__ float g_qkv[HH*HDIM + 2*KVH*HDIM];   // 3072
__device__ float g_q[HH*HDIM];
__device__ float g_attn[HH*HDIM];
__device__ float g_ff[FFD];
__device__ float g_vec[DD];
__device__ float g_pl[PLD];

__device__ __forceinline__ float gelu_tanh(float x) {
    const float c = 0.7978845608028654f;
    return 0.5f * x * (1.0f + tanhf(c * (x + 0.044715f * x * x * x)));
}

__device__ __forceinline__ float warp_sum(float v) {
#pragma unroll
    for (int o = 16; o; o >>= 1) v += __shfl_xor_sync(0xffffffffu, v, o);
    return v;
}

// ---------------- y = rms(x) * w (single block, n <= 2048) ----------------
__global__ void rms_scale_kernel(const float* __restrict__ x, const float* __restrict__ w,
                                 float* __restrict__ y, int n) {
    __shared__ float red[256];
    int t = threadIdx.x;
    float ss = 0.f;
    for (int i = t; i < n; i += 256) { float v = x[i]; ss += v * v; }
    red[t] = ss; __syncthreads();
    for (int s = 128; s > 0; s >>= 1) { if (t < s) red[t] += red[t + s]; __syncthreads(); }
    float r = rsqrtf(red[0] / (float)n + EPSF);
    for (int i = t; i < n; i += 256) y[i] = x[i] * r * w[i];
}

// ---------------- h += rms(tvec) * w ----------------
__global__ void ep_add_rms_kernel(const float* __restrict__ tv, const float* __restrict__ w,
                                  float* __restrict__ h, int n) {
    __shared__ float red[256];
    int t = threadIdx.x;
    float ss = 0.f;
    for (int i = t; i < n; i += 256) { float v = tv[i]; ss += v * v; }
    red[t] = ss; __syncthreads();
    for (int s = 128; s > 0; s >>= 1) { if (t < s) red[t] += red[t + s]; __syncthreads(); }
    float r = rsqrtf(red[0] / (float)n + EPSF);
    for (int i = t; i < n; i += 256) h[i] += tv[i] * r * w[i];
}

// ---------------- h = (h + rms(tvec) * w) * sc ----------------
__global__ void ep_final_kernel(const float* __restrict__ tv, const float* __restrict__ w,
                                float* __restrict__ h, const float* __restrict__ scp, int n) {
    __shared__ float red[256];
    int t = threadIdx.x;
    float ss = 0.f;
    for (int i = t; i < n; i += 256) { float v = tv[i]; ss += v * v; }
    red[t] = ss; __syncthreads();
    for (int s = 128; s > 0; s >>= 1) { if (t < s) red[t] += red[t + s]; __syncthreads(); }
    float r = rsqrtf(red[0] / (float)n + EPSF);
    float sc = scp[0];
    for (int i = t; i < n; i += 256) h[i] = (h[i] + tv[i] * r * w[i]) * sc;
}

// ---------------- generic GEMV: y = W @ x ; op==1 -> y = gelu(Wx)*aux[row] ----------------
// 256 threads = 8 warps, warp per row. x cached in dynamic smem.
__global__ void gemv_kernel(const float* __restrict__ W, const float* __restrict__ x,
                            float* __restrict__ y, int rows, int cols,
                            int op, const float* __restrict__ aux) {
    extern __shared__ float sx[];
    int n4 = cols >> 2;
    float4* sx4 = (float4*)sx;
    const float4* x4 = (const float4*)x;
    for (int i = threadIdx.x; i < n4; i += blockDim.x) sx4[i] = x4[i];
    __syncthreads();
    int row = blockIdx.x * 8 + (threadIdx.x >> 5);
    int lane = threadIdx.x & 31;
    if (row >= rows) return;
    const float4* Wr = (const float4*)(W + (size_t)row * cols);
    float acc = 0.f;
    for (int i = lane; i < n4; i += 32) {
        float4 w = Wr[i]; float4 v = sx4[i];
        acc = fmaf(w.x, v.x, acc); acc = fmaf(w.y, v.y, acc);
        acc = fmaf(w.z, v.z, acc); acc = fmaf(w.w, v.w, acc);
    }
    acc = warp_sum(acc);
    if (lane == 0) {
        if (op == 1) acc = gelu_tanh(acc) * aux[row];
        y[row] = acc;
    }
}

// ---------------- gated MLP GEMV: y = gelu(Wg x) * (Wu x) ----------------
__global__ void gemv_gated_kernel(const float* __restrict__ Wg, const float* __restrict__ Wu,
                                  const float* __restrict__ x, float* __restrict__ y,
                                  int rows, int cols) {
    extern __shared__ float sx[];
    int n4 = cols >> 2;
    float4* sx4 = (float4*)sx;
    const float4* x4 = (const float4*)x;
    for (int i = threadIdx.x; i < n4; i += blockDim.x) sx4[i] = x4[i];
    __syncthreads();
    int row = blockIdx.x * 8 + (threadIdx.x >> 5);
    int lane = threadIdx.x & 31;
    if (row >= rows) return;
    const float4* Wgr = (const float4*)(Wg + (size_t)row * cols);
    const float4* Wur = (const float4*)(Wu + (size_t)row * cols);
    float ag = 0.f, au = 0.f;
    for (int i = lane; i < n4; i += 32) {
        float4 v = sx4[i];
        float4 a = Wgr[i];
        ag = fmaf(a.x, v.x, ag); ag = fmaf(a.y, v.y, ag);
        ag = fmaf(a.z, v.z, ag); ag = fmaf(a.w, v.w, ag);
        float4 b = Wur[i];
        au = fmaf(b.x, v.x, au); au = fmaf(b.y, v.y, au);
        au = fmaf(b.z, v.z, au); au = fmaf(b.w, v.w, au);
    }
#pragma unroll
    for (int o = 16; o; o >>= 1) {
        ag += __shfl_xor_sync(0xffffffffu, ag, o);
        au += __shfl_xor_sync(0xffffffffu, au, o);
    }
    if (lane == 0) y[row] = gelu_tanh(ag) * au;
}

// ---------------- per-head RMS + scale + RoPE + cache write ----------------
// blocks 0..7 : q heads -> g_q ; blocks 8..9 : k heads -> Kpos ; blocks 10..11 : v -> Vpos
__global__ void qkv_post_kernel(const float* __restrict__ qkv,
                                const float* __restrict__ qn, const float* __restrict__ kn,
                                const float* __restrict__ cosv, const float* __restrict__ sinv,
                                float* __restrict__ q_out,
                                float* __restrict__ Kpos, float* __restrict__ Vpos) {
    __shared__ float sv[HDIM];
    __shared__ float red[HDIM];
    int b = blockIdx.x;
    int t = threadIdx.x;
    const float* src;
    if (b < 8)       src = qkv + b * HDIM;
    else if (b < 10) src = qkv + HH * HDIM + (b - 8) * HDIM;
    else             src = qkv + HH * HDIM + KVH * HDIM + (b - 10) * HDIM;
    float v = src[t];
    red[t] = v * v; __syncthreads();
    for (int s = 128; s > 0; s >>= 1) { if (t < s) red[t] += red[t + s]; __syncthreads(); }
    float r = rsqrtf(red[0] / (float)HDIM + EPSF);
    float val = v * r;
    if (b < 8)       val *= qn[t];
    else if (b < 10) val *= kn[t];
    sv[t] = val;
    __syncthreads();
    if (b < 10) {  // rope for q and k
        float rot = (t < 128) ? -sv[t + 128] : sv[t - 128];
        val = sv[t] * cosv[t] + rot * sinv[t];
    }
    if (b < 8)       q_out[b * HDIM + t] = val;
    else if (b < 10) Kpos[(size_t)(b - 8) * SS * HDIM + t] = val;
    else             Vpos[(size_t)(b - 10) * SS * HDIM + t] = val;
}

// ---------------- attention: one block per q head, per-warp online softmax ----------------
__global__ void attn_kernel(const float* __restrict__ q,
                            const float* __restrict__ Kl, const float* __restrict__ Vl,
                            float* __restrict__ out) {
    int h = blockIdx.x;
    int kv = h >> 2;  // N_REP = 4
    const float* Kh = Kl + (size_t)kv * SS * HDIM;
    const float* Vh = Vl + (size_t)kv * SS * HDIM;
    int warp = threadIdx.x >> 5, lane = threadIdx.x & 31;
    __shared__ float sq[HDIM];
    sq[threadIdx.x] = q[h * HDIM + threadIdx.x];
    __syncthreads();
    float qr[8];
#pragma unroll
    for (int j = 0; j < 8; j++) qr[j] = sq[lane * 8 + j];
    float m = -1e30f, lsum = 0.f;
    float acc[8] = {0.f, 0.f, 0.f, 0.f, 0.f, 0.f, 0.f, 0.f};
    for (int s = warp; s <= POSI; s += 8) {
        const float4* kp = (const float4*)(Kh + (size_t)s * HDIM + lane * 8);
        float4 k0 = kp[0], k1 = kp[1];
        float d = k0.x * qr[0] + k0.y * qr[1] + k0.z * qr[2] + k0.w * qr[3]
                + k1.x * qr[4] + k1.y * qr[5] + k1.z * qr[6] + k1.w * qr[7];
        d = warp_sum(d);
        float nm = fmaxf(m, d);
        float f = expf(m - nm);
        float p = expf(d - nm);
        lsum = lsum * f + p;
        const float4* vp = (const float4*)(Vh + (size_t)s * HDIM + lane * 8);
        float4 v0 = vp[0], v1 = vp[1];
        acc[0] = acc[0] * f + p * v0.x; acc[1] = acc[1] * f + p * v0.y;
        acc[2] = acc[2] * f + p * v0.z; acc[3] = acc[3] * f + p * v0.w;
        acc[4] = acc[4] * f + p * v1.x; acc[5] = acc[5] * f + p * v1.y;
        acc[6] = acc[6] * f + p * v1.z; acc[7] = acc[7] * f + p * v1.w;
        m = nm;
    }
    __shared__ float sm[8], sl[8], sacc[8][HDIM];
    if (lane == 0) { sm[warp] = m; sl[warp] = lsum; }
#pragma unroll
    for (int j = 0; j < 8; j++) sacc[warp][lane * 8 + j] = acc[j];
    __syncthreads();
    int t = threadIdx.x;
    float M = sm[0];
#pragma unroll
    for (int w = 1; w < 8; w++) M = fmaxf(M, sm[w]);
    float Ltot = 0.f, num = 0.f;
#pragma unroll
    for (int w = 0; w < 8; w++) {
        float f = expf(sm[w] - M);
        Ltot += sl[w] * f;
        num += sacc[w][t] * f;
    }
    out[h * HDIM + t] = num / Ltot;
}

// ==================================================================================
extern "C" void kernel_launch(void* const* d_in, const int* in_sizes, int n_in,
                              void* d_out, int out_size) {
    const float* hidden = (const float*)d_in[0];
    const float* pls    = (const float*)d_in[3];   // (L, PL) flattened
    const float* cos_s  = (const float*)d_in[4];
    const float* sin_s  = (const float*)d_in[5];
    const float* cos_f  = (const float*)d_in[6];
    const float* sin_f  = (const float*)d_in[7];
    const float* K_in   = (const float*)d_in[8];
    const float* V_in   = (const float*)d_in[9];
    const float* Wq     = (const float*)d_in[10];
    const float* Wk     = (const float*)d_in[11];
    const float* Wv     = (const float*)d_in[12];
    const float* Wo     = (const float*)d_in[13];
    const float* qn     = (const float*)d_in[14];
    const float* kn     = (const float*)d_in[15];
    const float* ln_in  = (const float*)d_in[16];
    const float* ln_pa  = (const float*)d_in[17];
    const float* ln_pre = (const float*)d_in[18];
    const float* ln_post= (const float*)d_in[19];
    const float* ln_pl  = (const float*)d_in[20];
    const float* Wg     = (const float*)d_in[21];
    const float* Wu     = (const float*)d_in[22];
    const float* Wd     = (const float*)d_in[23];
    const float* Wplg   = (const float*)d_in[24];
    const float* Wplp   = (const float*)d_in[25];
    const float* lsc    = (const float*)d_in[26];

    float* out  = (float*)d_out;
    float* outK = out + DD;
    float* outV = outK + (size_t)LL * KVH * SS * HDIM;

    float *h_, *hn_, *qkv_, *q_, *attn_, *ff_, *vec_, *pl_;
    cudaGetSymbolAddress((void**)&h_,    g_h);
    cudaGetSymbolAddress((void**)&hn_,   g_hn);
    cudaGetSymbolAddress((void**)&qkv_,  g_qkv);
    cudaGetSymbolAddress((void**)&q_,    g_q);
    cudaGetSymbolAddress((void**)&attn_, g_attn);
    cudaGetSymbolAddress((void**)&ff_,   g_ff);
    cudaGetSymbolAddress((void**)&vec_,  g_vec);
    cudaGetSymbolAddress((void**)&pl_,   g_pl);

    const size_t kvBytes = (size_t)LL * KVH * SS * HDIM * sizeof(float);
    cudaMemcpyAsync(outK, K_in, kvBytes, cudaMemcpyDeviceToDevice);
    cudaMemcpyAsync(outV, V_in, kvBytes, cudaMemcpyDeviceToDevice);
    cudaMemcpyAsync(h_, hidden, DD * sizeof(float), cudaMemcpyDeviceToDevice);

    for (int l = 0; l < LL; l++) {
        // is_full: (l+1)%5==0 -> only layer 4 for L=8 (deterministic in setup_inputs)
        const float* cosp = (l == 4) ? cos_f : cos_s;
        const float* sinp = (l == 4) ? sin_f : sin_s;

        const float* Wq_l   = Wq   + (size_t)l * HH * HDIM * DD;
        const float* Wk_l   = Wk   + (size_t)l * KVH * HDIM * DD;
        const float* Wv_l   = Wv   + (size_t)l * KVH * HDIM * DD;
        const float* Wo_l   = Wo   + (size_t)l * DD * HH * HDIM;
        const float* Wg_l   = Wg   + (size_t)l * FFD * DD;
        const float* Wu_l   = Wu   + (size_t)l * FFD * DD;
        const float* Wd_l   = Wd   + (size_t)l * DD * FFD;
        const float* Wplg_l = Wplg + (size_t)l * PLD * DD;
        const float* Wplp_l = Wplp + (size_t)l * DD * PLD;

        float* Kl   = outK + (size_t)l * KVH * SS * HDIM;
        float* Vl   = outV + (size_t)l * KVH * SS * HDIM;
        float* Kpos = Kl + (size_t)POSI * HDIM;
        float* Vpos = Vl + (size_t)POSI * HDIM;

        // attention block
        rms_scale_kernel<<<1, 256>>>(h_, ln_in + l * DD, hn_, DD);
        gemv_kernel<<<HH * HDIM / 8, 256, DD * 4>>>(Wq_l, hn_, qkv_, HH * HDIM, DD, 0, nullptr);
        gemv_kernel<<<KVH * HDIM / 8, 256, DD * 4>>>(Wk_l, hn_, qkv_ + HH * HDIM, KVH * HDIM, DD, 0, nullptr);
        gemv_kernel<<<KVH * HDIM / 8, 256, DD * 4>>>(Wv_l, hn_, qkv_ + HH * HDIM + KVH * HDIM, KVH * HDIM, DD, 0, nullptr);
        qkv_post_kernel<<<12, 256>>>(qkv_, qn + l * HDIM, kn + l * HDIM, cosp, sinp, q_, Kpos, Vpos);
        attn_kernel<<<HH, 256>>>(q_, Kl, Vl, attn_);
        gemv_kernel<<<DD / 8, 256, DD * 4>>>(Wo_l, attn_, vec_, DD, DD, 0, nullptr);
        ep_add_rms_kernel<<<1, 256>>>(vec_, ln_pa + l * DD, h_, DD);

        // MLP block
        rms_scale_kernel<<<1, 256>>>(h_, ln_pre + l * DD, hn_, DD);
        gemv_gated_kernel<<<FFD / 8, 256, DD * 4>>>(Wg_l, Wu_l, hn_, ff_, FFD, DD);
        gemv_kernel<<<DD / 8, 256, FFD * 4>>>(Wd_l, ff_, vec_, DD, FFD, 0, nullptr);
        ep_add_rms_kernel<<<1, 256>>>(vec_, ln_post + l * DD, h_, DD);

        // per-layer embedding block (uses h directly, no pre-norm)
        gemv_kernel<<<PLD / 8, 256, DD * 4>>>(Wplg_l, h_, pl_, PLD, DD, 1, pls + l * PLD);
        gemv_kernel<<<DD / 8, 256, PLD * 4>>>(Wplp_l, pl_, vec_, DD, PLD, 0, nullptr);
        ep_final_kernel<<<1, 256>>>(vec_, ln_pl + l * DD, h_, lsc + l, DD);
    }

    cudaMemcpyAsync(out, h_, DD * sizeof(float), cudaMemcpyDeviceToDevice);
}

// round 2
// speedup vs baseline: 3.5375x; 3.5375x over previous
#include <cuda_runtime.h>
#include <math.h>

#define DD   2048
#define HH   8
#define KVH  2
#define HDIM 256
#define SS   4096
#define FFD  8192
#define PLD  256
#define LL   8
#define POSI 2048
#define EPSF 1e-6f
#define NSPL 16
#define CHNK 129   // 16*129 = 2064 >= 2049 positions

// ---------------- scratch (device globals; no allocation allowed) ----------------
__device__ float g_h[DD];
__device__ float g_hn[DD];
__device__ float g_qkv[HH*HDIM + 2*KVH*HDIM];   // 3072
__device__ float g_q[HH*HDIM];
__device__ float g_attn[HH*HDIM];
__device__ float g_ff[FFD];
__device__ float g_vec[DD];
__device__ float g_pl[PLD];
__device__ float g_part[HH * NSPL * (HDIM + 2)];

__device__ __forceinline__ float gelu_tanh(float x) {
    const float c = 0.7978845608028654f;
    return 0.5f * x * (1.0f + tanhf(c * (x + 0.044715f * x * x * x)));
}

__device__ __forceinline__ float warp_sum(float v) {
#pragma unroll
    for (int o = 16; o; o >>= 1) v += __shfl_xor_sync(0xffffffffu, v, o);
    return v;
}

__device__ __forceinline__ float block_reduce_256(float v, float* red) {
    int t = threadIdx.x;
    red[t] = v; __syncthreads();
    for (int s = 128; s > 0; s >>= 1) { if (t < s) red[t] += red[t + s]; __syncthreads(); }
    float r = red[0];
    __syncthreads();
    return r;
}

// ---------------- hn = rms(h) * w ----------------
__global__ void norm_kernel(const float* __restrict__ h, const float* __restrict__ w,
                            float* __restrict__ hn) {
    __shared__ float red[256];
    int t = threadIdx.x;
    float hv[8]; float ss = 0.f;
#pragma unroll
    for (int j = 0; j < 8; j++) { hv[j] = h[t + j * 256]; ss += hv[j] * hv[j]; }
    ss = block_reduce_256(ss, red);
    float r = rsqrtf(ss / (float)DD + EPSF);
#pragma unroll
    for (int j = 0; j < 8; j++) { int i = t + j * 256; hn[i] = hv[j] * r * w[i]; }
}

// ---------------- h += rms(vec)*w1 ; optional hn = rms(h)*w2 ----------------
__global__ void add_rms_norm_kernel(const float* __restrict__ vec, const float* __restrict__ w1,
                                    float* __restrict__ h,
                                    const float* __restrict__ w2, float* __restrict__ hn) {
    __shared__ float red[256];
    int t = threadIdx.x;
    float vv[8], hv[8]; float ss = 0.f;
#pragma unroll
    for (int j = 0; j < 8; j++) { int i = t + j * 256; vv[j] = vec[i]; ss += vv[j] * vv[j]; }
    ss = block_reduce_256(ss, red);
    float r1 = rsqrtf(ss / (float)DD + EPSF);
    float ss2 = 0.f;
#pragma unroll
    for (int j = 0; j < 8; j++) {
        int i = t + j * 256;
        hv[j] = h[i] + vv[j] * r1 * w1[i];
        h[i] = hv[j];
        ss2 += hv[j] * hv[j];
    }
    if (w2) {
        ss2 = block_reduce_256(ss2, red);
        float r2 = rsqrtf(ss2 / (float)DD + EPSF);
#pragma unroll
        for (int j = 0; j < 8; j++) { int i = t + j * 256; hn[i] = hv[j] * r2 * w2[i]; }
    }
}

// ---------------- h = (h + rms(vec)*w) * sc ; optional hn = rms(h)*w2 ----------------
__global__ void ep_final_norm_kernel(const float* __restrict__ vec, const float* __restrict__ w,
                                     float* __restrict__ h, const float* __restrict__ scp,
                                     const float* __restrict__ w2, float* __restrict__ hn) {
    __shared__ float red[256];
    int t = threadIdx.x;
    float vv[8], hv[8]; float ss = 0.f;
#pragma unroll
    for (int j = 0; j < 8; j++) { int i = t + j * 256; vv[j] = vec[i]; ss += vv[j] * vv[j]; }
    ss = block_reduce_256(ss, red);
    float r1 = rsqrtf(ss / (float)DD + EPSF);
    float sc = scp[0];
    float ss2 = 0.f;
#pragma unroll
    for (int j = 0; j < 8; j++) {
        int i = t + j * 256;
        hv[j] = (h[i] + vv[j] * r1 * w[i]) * sc;
        h[i] = hv[j];
        ss2 += hv[j] * hv[j];
    }
    if (w2) {
        ss2 = block_reduce_256(ss2, red);
        float r2 = rsqrtf(ss2 / (float)DD + EPSF);
#pragma unroll
        for (int j = 0; j < 8; j++) { int i = t + j * 256; hn[i] = hv[j] * r2 * w2[i]; }
    }
}

// ---------------- generic fat GEMV: 512 threads, warp-per-row ----------------
template<int COLS>
__global__ void __launch_bounds__(512) gemv512_kernel(
        const float* __restrict__ W, const float* __restrict__ x,
        float* __restrict__ y, int rows, int op, const float* __restrict__ aux) {
    __shared__ float4 sx4[COLS / 4];
    const float4* x4 = (const float4*)x;
    for (int i = threadIdx.x; i < COLS / 4; i += 512) sx4[i] = x4[i];
    __syncthreads();
    int row = blockIdx.x * 16 + (threadIdx.x >> 5);
    if (row >= rows) return;
    int lane = threadIdx.x & 31;
    const float4* Wr = (const float4*)(W + (size_t)row * COLS);
    float acc = 0.f;
#pragma unroll 4
    for (int i = lane; i < COLS / 4; i += 32) {
        float4 w = Wr[i]; float4 v = sx4[i];
        acc = fmaf(w.x, v.x, acc); acc = fmaf(w.y, v.y, acc);
        acc = fmaf(w.z, v.z, acc); acc = fmaf(w.w, v.w, acc);
    }
    acc = warp_sum(acc);
    if (lane == 0) {
        if (op == 1) acc = gelu_tanh(acc) * aux[row];
        y[row] = acc;
    }
}

// ---------------- fused QKV GEMV: rows 0..2047 Wq, 2048..2559 Wk, 2560..3071 Wv ----------------
__global__ void __launch_bounds__(512) gemv_qkv_kernel(
        const float* __restrict__ Wq, const float* __restrict__ Wk, const float* __restrict__ Wv,
        const float* __restrict__ x, float* __restrict__ y) {
    __shared__ float4 sx4[DD / 4];
    const float4* x4 = (const float4*)x;
    for (int i = threadIdx.x; i < DD / 4; i += 512) sx4[i] = x4[i];
    __syncthreads();
    int row = blockIdx.x * 16 + (threadIdx.x >> 5);
    int lane = threadIdx.x & 31;
    const float* W; int r;
    if (row < 2048)      { W = Wq; r = row; }
    else if (row < 2560) { W = Wk; r = row - 2048; }
    else                 { W = Wv; r = row - 2560; }
    const float4* Wr = (const float4*)(W + (size_t)r * DD);
    float acc = 0.f;
#pragma unroll 4
    for (int i = lane; i < DD / 4; i += 32) {
        float4 w = Wr[i]; float4 v = sx4[i];
        acc = fmaf(w.x, v.x, acc); acc = fmaf(w.y, v.y, acc);
        acc = fmaf(w.z, v.z, acc); acc = fmaf(w.w, v.w, acc);
    }
    acc = warp_sum(acc);
    if (lane == 0) y[row] = acc;
}

// ---------------- fused gated MLP GEMV: y = gelu(Wg x) * (Wu x) ----------------
__global__ void __launch_bounds__(512) gemv_gated_kernel(
        const float* __restrict__ Wg, const float* __restrict__ Wu,
        const float* __restrict__ x, float* __restrict__ y) {
    __shared__ float4 sx4[DD / 4];
    const float4* x4 = (const float4*)x;
    for (int i = threadIdx.x; i < DD / 4; i += 512) sx4[i] = x4[i];
    __syncthreads();
    int row = blockIdx.x * 16 + (threadIdx.x >> 5);
    int lane = threadIdx.x & 31;
    const float4* Wgr = (const float4*)(Wg + (size_t)row * DD);
    const float4* Wur = (const float4*)(Wu + (size_t)row * DD);
    float ag = 0.f, au = 0.f;
#pragma unroll 2
    for (int i = lane; i < DD / 4; i += 32) {
        float4 v = sx4[i];
        float4 a = Wgr[i];
        ag = fmaf(a.x, v.x, ag); ag = fmaf(a.y, v.y, ag);
        ag = fmaf(a.z, v.z, ag); ag = fmaf(a.w, v.w, ag);
        float4 b = Wur[i];
        au = fmaf(b.x, v.x, au); au = fmaf(b.y, v.y, au);
        au = fmaf(b.z, v.z, au); au = fmaf(b.w, v.w, au);
    }
#pragma unroll
    for (int o = 16; o; o >>= 1) {
        ag += __shfl_xor_sync(0xffffffffu, ag, o);
        au += __shfl_xor_sync(0xffffffffu, au, o);
    }
    if (lane == 0) y[row] = gelu_tanh(ag) * au;
}

// ---------------- per-head RMS + scale + RoPE + cache write ----------------
__global__ void qkv_post_kernel(const float* __restrict__ qkv,
                                const float* __restrict__ qn, const float* __restrict__ kn,
                                const float* __restrict__ cosv, const float* __restrict__ sinv,
                                float* __restrict__ q_out,
                                float* __restrict__ Kpos, float* __restrict__ Vpos) {
    __shared__ float sv[HDIM];
    __shared__ float red[HDIM];
    int b = blockIdx.x;
    int t = threadIdx.x;
    const float* src;
    if (b < 8)       src = qkv + b * HDIM;
    else if (b < 10) src = qkv + HH * HDIM + (b - 8) * HDIM;
    else             src = qkv + HH * HDIM + KVH * HDIM + (b - 10) * HDIM;
    float v = src[t];
    red[t] = v * v; __syncthreads();
    for (int s = 128; s > 0; s >>= 1) { if (t < s) red[t] += red[t + s]; __syncthreads(); }
    float r = rsqrtf(red[0] / (float)HDIM + EPSF);
    float val = v * r;
    if (b < 8)       val *= qn[t];
    else if (b < 10) val *= kn[t];
    sv[t] = val;
    __syncthreads();
    if (b < 10) {
        float rot = (t < 128) ? -sv[t + 128] : sv[t - 128];
        val = sv[t] * cosv[t] + rot * sinv[t];
    }
    if (b < 8)       q_out[b * HDIM + t] = val;
    else if (b < 10) Kpos[(size_t)(b - 8) * SS * HDIM + t] = val;
    else             Vpos[(size_t)(b - 10) * SS * HDIM + t] = val;
}

// ---------------- attention pass 1: per-(head, chunk) partial online softmax ----------------
__global__ void attn_part_kernel(const float* __restrict__ q,
                                 const float* __restrict__ Kl, const float* __restrict__ Vl,
                                 float* __restrict__ part) {
    int h = blockIdx.x >> 4;
    int chunk = blockIdx.x & 15;
    int kv = h >> 2;  // N_REP = 4
    const float* Kh = Kl + (size_t)kv * SS * HDIM;
    const float* Vh = Vl + (size_t)kv * SS * HDIM;
    int warp = threadIdx.x >> 5, lane = threadIdx.x & 31;
    int s0 = chunk * CHNK;
    int sEnd = min(s0 + CHNK, POSI + 1);
    __shared__ float sq[HDIM];
    sq[threadIdx.x] = q[h * HDIM + threadIdx.x];
    __syncthreads();
    float qr[8];
#pragma unroll
    for (int j = 0; j < 8; j++) qr[j] = sq[lane * 8 + j];
    float m = -1e30f, lsum = 0.f;
    float acc[8] = {0.f,0.f,0.f,0.f,0.f,0.f,0.f,0.f};
    for (int s = s0 + warp; s < sEnd; s += 8) {
        const float4* kp = (const float4*)(Kh + (size_t)s * HDIM + lane * 8);
        float4 k0 = kp[0], k1 = kp[1];
        float d = k0.x * qr[0] + k0.y * qr[1] + k0.z * qr[2] + k0.w * qr[3]
                + k1.x * qr[4] + k1.y * qr[5] + k1.z * qr[6] + k1.w * qr[7];
        d = warp_sum(d);
        float nm = fmaxf(m, d);
        float f = expf(m - nm);
        float p = expf(d - nm);
        lsum = lsum * f + p;
        const float4* vp = (const float4*)(Vh + (size_t)s * HDIM + lane * 8);
        float4 v0 = vp[0], v1 = vp[1];
        acc[0] = acc[0] * f + p * v0.x; acc[1] = acc[1] * f + p * v0.y;
        acc[2] = acc[2] * f + p * v0.z; acc[3] = acc[3] * f + p * v0.w;
        acc[4] = acc[4] * f + p * v1.x; acc[5] = acc[5] * f + p * v1.y;
        acc[6] = acc[6] * f + p * v1.z; acc[7] = acc[7] * f + p * v1.w;
        m = nm;
    }
    __shared__ float sm[8], sl[8], sacc[8][HDIM];
    if (lane == 0) { sm[warp] = m; sl[warp] = lsum; }
#pragma unroll
    for (int j = 0; j < 8; j++) sacc[warp][lane * 8 + j] = acc[j];
    __syncthreads();
    int t = threadIdx.x;
    float M = sm[0];
#pragma unroll
    for (int w = 1; w < 8; w++) M = fmaxf(M, sm[w]);
    float Ltot = 0.f, num = 0.f;
#pragma unroll
    for (int w = 0; w < 8; w++) {
        float f = expf(sm[w] - M);
        Ltot += sl[w] * f;
        num += sacc[w][t] * f;
    }
    float* pp = part + (size_t)(h * NSPL + chunk) * (HDIM + 2);
    pp[t] = num;
    if (t == 0) { pp[HDIM] = M; pp[HDIM + 1] = Ltot; }
}

// ---------------- attention pass 2: combine chunks ----------------
__global__ void attn_comb_kernel(const float* __restrict__ part, float* __restrict__ out) {
    int h = blockIdx.x;
    int t = threadIdx.x;
    __shared__ float sm2[NSPL], sl2[NSPL];
    if (t < NSPL) {
        const float* pp = part + (size_t)(h * NSPL + t) * (HDIM + 2);
        sm2[t] = pp[HDIM]; sl2[t] = pp[HDIM + 1];
    }
    __syncthreads();
    float M = -1e30f;
#pragma unroll
    for (int c = 0; c < NSPL; c++) M = fmaxf(M, sm2[c]);
    float L = 0.f, num = 0.f;
#pragma unroll
    for (int c = 0; c < NSPL; c++) {
        float f = expf(sm2[c] - M);
        L += sl2[c] * f;
        num += part[(size_t)(h * NSPL + c) * (HDIM + 2) + t] * f;
    }
    out[h * HDIM + t] = num / L;
}

// ==================================================================================
extern "C" void kernel_launch(void* const* d_in, const int* in_sizes, int n_in,
                              void* d_out, int out_size) {
    const float* hidden = (const float*)d_in[0];
    const float* pls    = (const float*)d_in[3];
    const float* cos_s  = (const float*)d_in[4];
    const float* sin_s  = (const float*)d_in[5];
    const float* cos_f  = (const float*)d_in[6];
    const float* sin_f  = (const float*)d_in[7];
    const float* K_in   = (const float*)d_in[8];
    const float* V_in   = (const float*)d_in[9];
    const float* Wq     = (const float*)d_in[10];
    const float* Wk     = (const float*)d_in[11];
    const float* Wv     = (const float*)d_in[12];
    const float* Wo     = (const float*)d_in[13];
    const float* qn     = (const float*)d_in[14];
    const float* kn     = (const float*)d_in[15];
    const float* ln_in  = (const float*)d_in[16];
    const float* ln_pa  = (const float*)d_in[17];
    const float* ln_pre = (const float*)d_in[18];
    const float* ln_post= (const float*)d_in[19];
    const float* ln_pl  = (const float*)d_in[20];
    const float* Wg     = (const float*)d_in[21];
    const float* Wu     = (const float*)d_in[22];
    const float* Wd     = (const float*)d_in[23];
    const float* Wplg   = (const float*)d_in[24];
    const float* Wplp   = (const float*)d_in[25];
    const float* lsc    = (const float*)d_in[26];

    float* out  = (float*)d_out;
    float* outK = out + DD;
    float* outV = outK + (size_t)LL * KVH * SS * HDIM;

    float *h_, *hn_, *qkv_, *q_, *attn_, *ff_, *vec_, *pl_, *part_;
    cudaGetSymbolAddress((void**)&h_,    g_h);
    cudaGetSymbolAddress((void**)&hn_,   g_hn);
    cudaGetSymbolAddress((void**)&qkv_,  g_qkv);
    cudaGetSymbolAddress((void**)&q_,    g_q);
    cudaGetSymbolAddress((void**)&attn_, g_attn);
    cudaGetSymbolAddress((void**)&ff_,   g_ff);
    cudaGetSymbolAddress((void**)&vec_,  g_vec);
    cudaGetSymbolAddress((void**)&pl_,   g_pl);
    cudaGetSymbolAddress((void**)&part_, g_part);

    const size_t kvBytes = (size_t)LL * KVH * SS * HDIM * sizeof(float);
    cudaMemcpyAsync(outK, K_in, kvBytes, cudaMemcpyDeviceToDevice);
    cudaMemcpyAsync(outV, V_in, kvBytes, cudaMemcpyDeviceToDevice);
    cudaMemcpyAsync(h_, hidden, DD * sizeof(float), cudaMemcpyDeviceToDevice);

    norm_kernel<<<1, 256>>>(h_, ln_in, hn_);   // layer-0 pre-norm

    for (int l = 0; l < LL; l++) {
        const float* cosp = (l == 4) ? cos_f : cos_s;   // is_full only for layer 4
        const float* sinp = (l == 4) ? sin_f : sin_s;

        const float* Wq_l   = Wq   + (size_t)l * HH * HDIM * DD;
        const float* Wk_l   = Wk   + (size_t)l * KVH * HDIM * DD;
        const float* Wv_l   = Wv   + (size_t)l * KVH * HDIM * DD;
        const float* Wo_l   = Wo   + (size_t)l * DD * HH * HDIM;
        const float* Wg_l   = Wg   + (size_t)l * FFD * DD;
        const float* Wu_l   = Wu   + (size_t)l * FFD * DD;
        const float* Wd_l   = Wd   + (size_t)l * DD * FFD;
        const float* Wplg_l = Wplg + (size_t)l * PLD * DD;
        const float* Wplp_l = Wplp + (size_t)l * DD * PLD;

        float* Kl   = outK + (size_t)l * KVH * SS * HDIM;
        float* Vl   = outV + (size_t)l * KVH * SS * HDIM;
        float* Kpos = Kl + (size_t)POSI * HDIM;
        float* Vpos = Vl + (size_t)POSI * HDIM;

        // attention block
        gemv_qkv_kernel<<<192, 512>>>(Wq_l, Wk_l, Wv_l, hn_, qkv_);
        qkv_post_kernel<<<12, 256>>>(qkv_, qn + l * HDIM, kn + l * HDIM, cosp, sinp, q_, Kpos, Vpos);
        attn_part_kernel<<<HH * NSPL, 256>>>(q_, Kl, Vl, part_);
        attn_comb_kernel<<<HH, 256>>>(part_, attn_);
        gemv512_kernel<DD><<<128, 512>>>(Wo_l, attn_, vec_, DD, 0, nullptr);
        add_rms_norm_kernel<<<1, 256>>>(vec_, ln_pa + l * DD, h_, ln_pre + l * DD, hn_);

        // MLP block
        gemv_gated_kernel<<<512, 512>>>(Wg_l, Wu_l, hn_, ff_);
        gemv512_kernel<FFD><<<128, 512>>>(Wd_l, ff_, vec_, DD, 0, nullptr);
        add_rms_norm_kernel<<<1, 256>>>(vec_, ln_post + l * DD, h_, nullptr, nullptr);

        // per-layer embedding block (uses h directly)
        gemv512_kernel<DD><<<16, 512>>>(Wplg_l, h_, pl_, PLD, 1, pls + l * PLD);
        gemv512_kernel<PLD><<<128, 512>>>(Wplp_l, pl_, vec_, DD, 0, nullptr);
        ep_final_norm_kernel<<<1, 256>>>(vec_, ln_pl + l * DD, h_, lsc + l,
                                         (l < LL - 1) ? (ln_in + (l + 1) * DD) : nullptr, hn_);
    }

    cudaMemcpyAsync(out, h_, DD * sizeof(float), cudaMemcpyDeviceToDevice);
}